// round 7
// baseline (speedup 1.0000x reference)
#include <cuda_runtime.h>
#include <cstdint>

typedef unsigned long long ull;

#define NROWS   32768      // rows per input tensor (8*64*64)
#define DIMD    256        // feature dim
#define KC      1024       // codebook size

// output layout (float32, tuple-concat order)
#define ESZ      8388608ull    // one ste block (NROWS*DIMD)
#define DSZ      33554432ull   // one dist block (NROWS*KC)
#define OFF_DIFF 33554432ull   // after 4 ste blocks
#define OFF_IND  33554436ull   // after 4 diff scalars
#define OFF_DIST 33685508ull   // after 4 ind blocks (4*32768)

// scratch (static device globals — no allocations)
__device__ __align__(16) ull    g_keys[2 * NROWS];
__device__ __align__(16) float  g_xsq[2 * NROWS];
__device__ __align__(16) float  g_esq[KC];
__device__ __align__(16) float  g_embT[KC * DIMD];
__device__ double g_diff[2];

__device__ __forceinline__ ull dup2(float x) {
    ull r; asm("mov.b64 %0, {%1, %1};" : "=l"(r) : "f"(x)); return r;
}
__device__ __forceinline__ ull fma2(ull a, ull b, ull c) {
    ull d; asm("fma.rn.f32x2 %0, %1, %2, %3;" : "=l"(d) : "l"(a), "l"(b), "l"(c)); return d;
}
__device__ __forceinline__ void cp_async16(uint32_t saddr, const void* gptr) {
    asm volatile("cp.async.ca.shared.global [%0], [%1], 16;" :: "r"(saddr), "l"(gptr));
}
__device__ __forceinline__ void cp_commit() { asm volatile("cp.async.commit_group;"); }
__device__ __forceinline__ void cp_wait0()  { asm volatile("cp.async.wait_group 0;"); }

union F4U { float4 f; ull u[2]; float s[4]; };
union ULF { ull u; float2 f; };

// ---------------------------------------------------------------- init
__global__ void k_init() {
    int i = blockIdx.x * blockDim.x + threadIdx.x;   // 65536 threads exactly
    g_keys[i] = ~0ull;
    if (i < 2) g_diff[i] = 0.0;
}

// ------------------------------------------------- per-row ||x||^2
// XLA-style row-reduce: per-lane strided (lane+32j) mul.rn+add.rn partials
// (no fma contraction), then shfl-DOWN tree; lane 0 holds the result.
__global__ void k_prep_rows(const float* __restrict__ hr, const float* __restrict__ lr) {
    int w    = blockIdx.x * (blockDim.x >> 5) + (threadIdx.x >> 5);   // 16384 warps
    int lane = threadIdx.x & 31;
#pragma unroll
    for (int i = 0; i < 4; i++) {
        int row = w + i * 16384;                                      // 0..65535
        const float* x = (row >= NROWS) ? (lr + (size_t)(row - NROWS) * DIMD)
                                        : (hr + (size_t)row * DIMD);
        float s = 0.f;
#pragma unroll
        for (int j = 0; j < 8; j++) {
            float v = x[lane + (j << 5)];
            s = __fadd_rn(s, __fmul_rn(v, v));
        }
#pragma unroll
        for (int o = 16; o > 0; o >>= 1)
            s = __fadd_rn(s, __shfl_down_sync(0xffffffffu, s, o));
        if (lane == 0) g_xsq[row] = s;
    }
}

// ----------------------------- per-code ||e||^2 + transposed codebook
__global__ void k_prep_embed(const float* __restrict__ embed) {
    int warp = blockIdx.x * (blockDim.x >> 5) + (threadIdx.x >> 5);   // 1024 warps
    int lane = threadIdx.x & 31;
    int c    = warp;                                                  // column 0..1023
    float s = 0.f;
#pragma unroll
    for (int i = 0; i < 8; i++) {
        int d = lane + (i << 5);
        float v = embed[(size_t)d * KC + c];
        g_embT[(size_t)c * DIMD + d] = v;
        s = __fadd_rn(s, __fmul_rn(v, v));
    }
#pragma unroll
    for (int o = 16; o > 0; o >>= 1)
        s = __fadd_rn(s, __shfl_down_sync(0xffffffffu, s, o));
    if (lane == 0) g_esq[c] = s;
}

// ------------------------------------------------ fused GEMM + dist + argmin
// 128x128 tile, BK=8, double-buffered (cp.async B, LDG+STS-transpose A),
// 256 threads, 8x8 micro-tile, fp32x2 packed along M.
// Accumulation: single fma chain per (row,col), k ascending — bitwise
// identical to the previously-passing kernel.
__global__ __launch_bounds__(256, 2) void k_gemm(
    const float* __restrict__ hr, const float* __restrict__ lr,
    const float* __restrict__ embed, float* __restrict__ out)
{
    __shared__ float As[2][8][132];   // transposed, padded (conflict-free)
    __shared__ float Bs[2][8][128];
    __shared__ ull   skey[128];

    const int z       = blockIdx.z;
    const float* A    = z ? lr : hr;
    const int rowBase = blockIdx.y << 7;
    const int colBase = blockIdx.x << 7;
    const int tid     = threadIdx.x;
    const int tx      = tid & 15, ty = tid >> 4;

    // load-thread mapping (BK=8)
    const int ar = tid >> 1;               // A row 0..127
    const int ak = (tid & 1) << 2;         // A k-quad 0 or 4
    const int bd = tid >> 5;               // B k-row 0..7
    const int bc = (tid & 31) << 2;        // B col quad

    const float* Aptr = A + (size_t)(rowBase + ar) * DIMD + ak;
    const float* Bptr = embed + (size_t)bd * KC + colBase + bc;

    ull acc[4][8];
#pragma unroll
    for (int m = 0; m < 4; m++)
#pragma unroll
        for (int j = 0; j < 8; j++) acc[m][j] = 0ull;

    if (tid < 128) skey[tid] = ~0ull;

    // ---- prologue: stage 0
    {
        float4 av = *(const float4*)(Aptr);
        As[0][ak + 0][ar] = av.x; As[0][ak + 1][ar] = av.y;
        As[0][ak + 2][ar] = av.z; As[0][ak + 3][ar] = av.w;
        cp_async16((uint32_t)__cvta_generic_to_shared(&Bs[0][bd][bc]), Bptr);
        cp_commit();
    }

    const int NKB = DIMD / 8;   // 32
    for (int kb = 0; kb < NKB; kb++) {
        const int buf = kb & 1;
        // issue next A LDG before the barrier (independent of smem state)
        float4 av;
        if (kb + 1 < NKB) av = *(const float4*)(Aptr + (kb + 1) * 8);

        cp_wait0();
        __syncthreads();

        if (kb + 1 < NKB) {
            const int nb = buf ^ 1;
            As[nb][ak + 0][ar] = av.x; As[nb][ak + 1][ar] = av.y;
            As[nb][ak + 2][ar] = av.z; As[nb][ak + 3][ar] = av.w;
            cp_async16((uint32_t)__cvta_generic_to_shared(&Bs[nb][bd][bc]),
                       Bptr + (size_t)(kb + 1) * 8 * KC);
            cp_commit();
        }

#pragma unroll
        for (int k = 0; k < 8; k++) {
            F4U a0, a1, b0, b1;
            a0.f = *(const float4*)&As[buf][k][(ty << 3)];
            a1.f = *(const float4*)&As[buf][k][(ty << 3) + 4];
            b0.f = *(const float4*)&Bs[buf][k][(tx << 3)];
            b1.f = *(const float4*)&Bs[buf][k][(tx << 3) + 4];
            ull ap[4] = { a0.u[0], a0.u[1], a1.u[0], a1.u[1] };   // row pairs
            float bv[8] = { b0.s[0], b0.s[1], b0.s[2], b0.s[3],
                            b1.s[0], b1.s[1], b1.s[2], b1.s[3] };
#pragma unroll
            for (int j = 0; j < 8; j++) {
                ull bdp = dup2(bv[j]);
#pragma unroll
                for (int m = 0; m < 4; m++) acc[m][j] = fma2(ap[m], bdp, acc[m][j]);
            }
        }
        __syncthreads();
    }

    // epilogue: dist = (xsq - 2*S) + esq   [EXACT reference rounding order],
    // write both dup dist blocks; argmin key shfl-reduced across tx lanes
    // before one uncontended shared atomicMin.
    float esqv[8];
#pragma unroll
    for (int j = 0; j < 8; j++) esqv[j] = g_esq[colBase + (tx << 3) + j];

#pragma unroll
    for (int m = 0; m < 4; m++) {
#pragma unroll
        for (int h = 0; h < 2; h++) {
            int r    = (ty << 3) + (m << 1) + h;
            int grow = rowBase + r;
            float xs = g_xsq[(size_t)z * NROWS + grow];
            float v[8];
            ull best = ~0ull;
#pragma unroll
            for (int j = 0; j < 8; j++) {
                ULF q; q.u = acc[m][j];
                float sdot = h ? q.f.y : q.f.x;
                float dv = __fadd_rn(__fsub_rn(xs, __fmul_rn(2.f, sdot)), esqv[j]);
                v[j] = dv;
                ull key = ((ull)__float_as_uint(dv) << 32)
                        | (unsigned)(colBase + (tx << 3) + j);
                if (key < best) best = key;
            }
            // reduce across the 16 lanes (same r, different tx) — xor stays
            // inside each 16-lane half (lane bit4 = ty parity untouched)
#pragma unroll
            for (int o = 8; o > 0; o >>= 1) {
                ull other = __shfl_xor_sync(0xffffffffu, best, o);
                if (other < best) best = other;
            }
            if (tx == 0) atomicMin(&skey[r], best);

            size_t o1 = OFF_DIST + (size_t)z * DSZ + (size_t)grow * KC + colBase + (tx << 3);
            size_t o2 = o1 + 2 * DSZ;
            float4 s0 = make_float4(v[0], v[1], v[2], v[3]);
            float4 s1 = make_float4(v[4], v[5], v[6], v[7]);
            *(float4*)(out + o1)     = s0; *(float4*)(out + o1 + 4) = s1;
            *(float4*)(out + o2)     = s0; *(float4*)(out + o2 + 4) = s1;
        }
    }
    __syncthreads();
    if (tid < 128)
        atomicMin(&g_keys[(size_t)z * NROWS + rowBase + tid], skey[tid]);
}

// ------------------------------------ gather: ste = x + (q - x), ind, diff
__global__ void k_gather(const float* __restrict__ hr, const float* __restrict__ lr,
                         float* __restrict__ out)
{
    int w    = blockIdx.x * (blockDim.x >> 5) + (threadIdx.x >> 5);  // 65536 warps
    int lane = threadIdx.x & 31;
    int z    = w >> 15;
    int row  = w & 32767;
    const float* x = (z ? lr : hr) + (size_t)row * DIMD;
    ull key = g_keys[w];
    unsigned ind = (unsigned)(key & 0xffffffffull);
    const float* q = g_embT + (size_t)ind * DIMD;
    float* s1 = out + (size_t)z * ESZ + (size_t)row * DIMD;
    float* s2 = s1 + 2 * ESZ;
    float acc = 0.f;
#pragma unroll
    for (int j = 0; j < 8; j++) {
        int c  = lane + (j << 5);
        float xv = x[c];
        float qv = q[c];
        float d  = __fsub_rn(qv, xv);         // reference: quantize - input
        float sv = __fadd_rn(xv, d);          // reference STE: x + (q - x), bitwise
        acc = fmaf(d, d, acc);
        s1[c] = sv; s2[c] = sv;
    }
#pragma unroll
    for (int o = 16; o > 0; o >>= 1) acc += __shfl_xor_sync(0xffffffffu, acc, o);
    if (lane == 0) {
        atomicAdd(&g_diff[z], (double)acc);
        out[OFF_IND + (size_t)z * NROWS + row]            = (float)ind;
        out[OFF_IND + 65536ull + (size_t)z * NROWS + row] = (float)ind;
    }
}

// --------------------------------------------------------------- finalize
__global__ void k_final(float* __restrict__ out) {
    int t = threadIdx.x;
    if (t < 4) out[OFF_DIFF + t] = (float)(g_diff[t & 1] / 8388608.0);
}

extern "C" void kernel_launch(void* const* d_in, const int* in_sizes, int n_in,
                              void* d_out, int out_size)
{
    const float* hr = (const float*)d_in[0];
    const float* lr = (const float*)d_in[1];
    const float* em = (const float*)d_in[2];
    float* out = (float*)d_out;

    k_init<<<256, 256>>>();
    k_prep_rows<<<2048, 256>>>(hr, lr);
    k_prep_embed<<<128, 256>>>(em);
    dim3 g(KC / 128, NROWS / 128, 2);          // 8 x 256 x 2  (colTile fastest -> A reuse in L2)
    k_gemm<<<g, 256>>>(hr, lr, em, out);
    k_gather<<<8192, 256>>>(hr, lr, out);
    k_final<<<1, 32>>>(out);
}

// round 10
// speedup vs baseline: 1.4910x; 1.4910x over previous
#include <cuda_runtime.h>
#include <cuda_bf16.h>
#include <cstdint>

typedef unsigned long long ull;

#define NROWS   32768      // rows per input tensor (8*64*64)
#define DIMD    256        // feature dim
#define KC      1024       // codebook size

// output layout (float32, tuple-concat order) — verified by passing R6
#define ESZ      8388608ull    // one ste block (NROWS*DIMD)
#define DSZ      33554432ull   // one dist block (NROWS*KC)
#define OFF_DIFF 33554432ull   // after 4 ste blocks
#define OFF_IND  33554436ull   // after 4 diff scalars
#define OFF_DIST 33685508ull   // after 4 ind blocks (4*32768)

#define EPS_WIN  0.02f         // candidate window (>20x bf16 dist noise)

// scratch (static device globals — no allocations)
__device__ __align__(16) float  g_xsq[2 * NROWS];
__device__ __align__(16) float  g_esq[KC];
__device__ __align__(16) float  g_embT[KC * DIMD];
__device__ double g_diff[2];

__device__ __forceinline__ uint32_t bf2(float x, float y) {
    __nv_bfloat162 h = __floats2bfloat162_rn(x, y);   // low = x, high = y
    return *(uint32_t*)&h;
}

// ---------------------------------------------------------------- init
__global__ void k_init() {
    if (threadIdx.x < 2) g_diff[threadIdx.x] = 0.0;
}

// ------------------------------------------------- per-row ||x||^2
// BITWISE path (verified): strided mul.rn+add.rn partials, shfl-down tree.
__global__ void k_prep_rows(const float* __restrict__ hr, const float* __restrict__ lr) {
    int w    = blockIdx.x * (blockDim.x >> 5) + (threadIdx.x >> 5);   // 16384 warps
    int lane = threadIdx.x & 31;
#pragma unroll
    for (int i = 0; i < 4; i++) {
        int row = w + i * 16384;                                      // 0..65535
        const float* x = (row >= NROWS) ? (lr + (size_t)(row - NROWS) * DIMD)
                                        : (hr + (size_t)row * DIMD);
        float s = 0.f;
#pragma unroll
        for (int j = 0; j < 8; j++) {
            float v = x[lane + (j << 5)];
            s = __fadd_rn(s, __fmul_rn(v, v));
        }
#pragma unroll
        for (int o = 16; o > 0; o >>= 1)
            s = __fadd_rn(s, __shfl_down_sync(0xffffffffu, s, o));
        if (lane == 0) g_xsq[row] = s;
    }
}

// ----------------------------- per-code ||e||^2 + transposed fp32 codebook
__global__ void k_prep_embed(const float* __restrict__ embed) {
    int warp = blockIdx.x * (blockDim.x >> 5) + (threadIdx.x >> 5);   // 1024 warps
    int lane = threadIdx.x & 31;
    int c    = warp;
    float s = 0.f;
#pragma unroll
    for (int i = 0; i < 8; i++) {
        int d = lane + (i << 5);
        float v = embed[(size_t)d * KC + c];
        g_embT[(size_t)c * DIMD + d] = v;
        s = __fadd_rn(s, __fmul_rn(v, v));
    }
#pragma unroll
    for (int o = 16; o > 0; o >>= 1)
        s = __fadd_rn(s, __shfl_down_sync(0xffffffffu, s, o));
    if (lane == 0) g_esq[c] = s;
}

// ------------------------------------------------ bf16 HMMA GEMM -> dist~
// CTA 128x128, BK=32, 8 warps (warp tile 32x64), mma.sync m16n8k16 bf16.
// Writes ONLY the approximate dist blocks (x2 duplicates).
#define APITCH 40   // bf16 elems per smem row (banks: r*20 mod 32 all-distinct over 8 rows)

__global__ __launch_bounds__(256, 2) void k_gemm(
    const float* __restrict__ hr, const float* __restrict__ lr,
    const float* __restrict__ embed, float* __restrict__ out)
{
    __shared__ __nv_bfloat16 As[2][128][APITCH];   // [row][k]
    __shared__ __nv_bfloat16 Bs[2][128][APITCH];   // [col][k]  (transposed at stage)
    __shared__ float sxs[128], sesq[128];

    const int z       = blockIdx.z;
    const float* A    = z ? lr : hr;
    const int rowBase = blockIdx.y << 7;
    const int colBase = blockIdx.x << 7;
    const int tid     = threadIdx.x;
    const int lane    = tid & 31, wid = tid >> 5;
    const int wm      = wid >> 1, wn = wid & 1;       // warp grid 4x2
    const int gid     = lane >> 2, t4 = lane & 3;

    if (tid < 128) {
        sxs[tid]  = g_xsq[(size_t)z * NROWS + rowBase + tid];
        sesq[tid] = g_esq[colBase + tid];
    }

    // staging thread mapping
    const int ar = tid >> 1,        akh = (tid & 1) << 4;   // A: row, k-half(0/16)
    const int bk = tid >> 3,        bn0 = (tid & 7) << 4;   // B: k-row, n-base
    const float* Ap = A + (size_t)(rowBase + ar) * DIMD + akh;
    const float* Bp = embed + (size_t)bk * KC + colBase + bn0;

    float acc[2][8][4];
#pragma unroll
    for (int m = 0; m < 2; m++)
#pragma unroll
        for (int n = 0; n < 8; n++)
#pragma unroll
            for (int c = 0; c < 4; c++) acc[m][n][c] = 0.f;

    // ---- stage 0
    {
        float4 p0 = *(const float4*)(Ap + 0), p1 = *(const float4*)(Ap + 4);
        float4 p2 = *(const float4*)(Ap + 8), p3 = *(const float4*)(Ap + 12);
        uint4 u0 = { bf2(p0.x,p0.y), bf2(p0.z,p0.w), bf2(p1.x,p1.y), bf2(p1.z,p1.w) };
        uint4 u1 = { bf2(p2.x,p2.y), bf2(p2.z,p2.w), bf2(p3.x,p3.y), bf2(p3.z,p3.w) };
        *(uint4*)&As[0][ar][akh]     = u0;
        *(uint4*)&As[0][ar][akh + 8] = u1;
        float4 q0 = *(const float4*)(Bp + 0), q1 = *(const float4*)(Bp + 4);
        float4 q2 = *(const float4*)(Bp + 8), q3 = *(const float4*)(Bp + 12);
        float qs[16] = { q0.x,q0.y,q0.z,q0.w, q1.x,q1.y,q1.z,q1.w,
                         q2.x,q2.y,q2.z,q2.w, q3.x,q3.y,q3.z,q3.w };
#pragma unroll
        for (int i = 0; i < 16; i++)
            Bs[0][bn0 + i][bk] = __float2bfloat16_rn(qs[i]);
    }
    __syncthreads();

    for (int kb = 0; kb < 8; kb++) {
        const int buf = kb & 1;
        float4 p0, p1, p2, p3, q0, q1, q2, q3;
        if (kb < 7) {
            const float* An = Ap + (kb + 1) * 32;
            p0 = *(const float4*)(An + 0);  p1 = *(const float4*)(An + 4);
            p2 = *(const float4*)(An + 8);  p3 = *(const float4*)(An + 12);
            const float* Bn = Bp + (size_t)(kb + 1) * 32 * KC;
            q0 = *(const float4*)(Bn + 0);  q1 = *(const float4*)(Bn + 4);
            q2 = *(const float4*)(Bn + 8);  q3 = *(const float4*)(Bn + 12);
        }

#pragma unroll
        for (int ks = 0; ks < 2; ks++) {
            const int kk = ks * 16 + t4 * 2;
            uint32_t bfr[8][2];
#pragma unroll
            for (int n = 0; n < 8; n++) {
                const int col = wn * 64 + n * 8 + gid;
                bfr[n][0] = *(const uint32_t*)&Bs[buf][col][kk];
                bfr[n][1] = *(const uint32_t*)&Bs[buf][col][kk + 8];
            }
#pragma unroll
            for (int m = 0; m < 2; m++) {
                const int r0 = wm * 32 + m * 16 + gid;
                uint32_t a0 = *(const uint32_t*)&As[buf][r0][kk];
                uint32_t a1 = *(const uint32_t*)&As[buf][r0 + 8][kk];
                uint32_t a2 = *(const uint32_t*)&As[buf][r0][kk + 8];
                uint32_t a3 = *(const uint32_t*)&As[buf][r0 + 8][kk + 8];
#pragma unroll
                for (int n = 0; n < 8; n++) {
                    asm volatile(
                        "mma.sync.aligned.m16n8k16.row.col.f32.bf16.bf16.f32 "
                        "{%0,%1,%2,%3}, {%4,%5,%6,%7}, {%8,%9}, {%0,%1,%2,%3};"
                        : "+f"(acc[m][n][0]), "+f"(acc[m][n][1]),
                          "+f"(acc[m][n][2]), "+f"(acc[m][n][3])
                        : "r"(a0), "r"(a1), "r"(a2), "r"(a3),
                          "r"(bfr[n][0]), "r"(bfr[n][1]));
                }
            }
        }

        if (kb < 7) {
            const int nb = buf ^ 1;
            uint4 u0 = { bf2(p0.x,p0.y), bf2(p0.z,p0.w), bf2(p1.x,p1.y), bf2(p1.z,p1.w) };
            uint4 u1 = { bf2(p2.x,p2.y), bf2(p2.z,p2.w), bf2(p3.x,p3.y), bf2(p3.z,p3.w) };
            *(uint4*)&As[nb][ar][akh]     = u0;
            *(uint4*)&As[nb][ar][akh + 8] = u1;
            float qs[16] = { q0.x,q0.y,q0.z,q0.w, q1.x,q1.y,q1.z,q1.w,
                             q2.x,q2.y,q2.z,q2.w, q3.x,q3.y,q3.z,q3.w };
#pragma unroll
            for (int i = 0; i < 16; i++)
                Bs[nb][bn0 + i][bk] = __float2bfloat16_rn(qs[i]);
        }
        __syncthreads();
    }

    // epilogue: dist~ = xs - 2S + esq ; write both duplicate blocks
#pragma unroll
    for (int m = 0; m < 2; m++) {
#pragma unroll
        for (int half = 0; half < 2; half++) {
            const int r    = wm * 32 + m * 16 + gid + half * 8;
            const int grow = rowBase + r;
            const float xs = sxs[r];
            size_t rbase = OFF_DIST + (size_t)z * DSZ + (size_t)grow * KC + colBase;
#pragma unroll
            for (int n = 0; n < 8; n++) {
                const int lc = wn * 64 + n * 8 + t4 * 2;
                float s0 = acc[m][n][half * 2 + 0];
                float s1 = acc[m][n][half * 2 + 1];
                float2 dv = make_float2(fmaf(-2.f, s0, xs) + sesq[lc],
                                        fmaf(-2.f, s1, xs) + sesq[lc + 1]);
                *(float2*)(out + rbase + lc)           = dv;
                *(float2*)(out + rbase + lc + 2 * DSZ) = dv;
            }
        }
    }
}

// ---------------- post: exact argmin recheck + ste + ind + diff (warp/row)
__global__ __launch_bounds__(256) void k_post(
    const float* __restrict__ hr, const float* __restrict__ lr,
    float* __restrict__ out)
{
    __shared__ float xb[8][DIMD];
    __shared__ float eb[8][DIMD];

    const int wi   = threadIdx.x >> 5;
    const int lane = threadIdx.x & 31;
    const int w    = blockIdx.x * 8 + wi;          // 0..65535
    const int z    = w >> 15;
    const int row  = w & 32767;

    const float* x = (z ? lr : hr) + (size_t)row * DIMD;
    float xr[8];
    {
        float4 a = *(const float4*)(x + lane * 8);
        float4 b = *(const float4*)(x + lane * 8 + 4);
        xr[0]=a.x; xr[1]=a.y; xr[2]=a.z; xr[3]=a.w;
        xr[4]=b.x; xr[5]=b.y; xr[6]=b.z; xr[7]=b.w;
        *(float4*)&xb[wi][lane * 8]     = a;
        *(float4*)&xb[wi][lane * 8 + 4] = b;
    }
    const float xs = g_xsq[(size_t)z * NROWS + row];
    __syncwarp();

    // scan this row's approximate dists (already in out), find min + candidates
    const float* drow = out + OFF_DIST + (size_t)z * DSZ + (size_t)row * KC;
    float4 v[8];
    float mn = 3.4e38f;
#pragma unroll
    for (int j = 0; j < 8; j++) {
        v[j] = *(const float4*)(drow + j * 128 + lane * 4);
        mn = fminf(mn, fminf(fminf(v[j].x, v[j].y), fminf(v[j].z, v[j].w)));
    }
#pragma unroll
    for (int o = 16; o > 0; o >>= 1)
        mn = fminf(mn, __shfl_xor_sync(0xffffffffu, mn, o));
    const float thr = mn + EPS_WIN;

    unsigned cmask = 0;
#pragma unroll
    for (int j = 0; j < 8; j++) {
        if (v[j].x <= thr) cmask |= 1u << (j * 4 + 0);
        if (v[j].y <= thr) cmask |= 1u << (j * 4 + 1);
        if (v[j].z <= thr) cmask |= 1u << (j * 4 + 2);
        if (v[j].w <= thr) cmask |= 1u << (j * 4 + 3);
    }

    ull best = ~0ull;
    while (true) {
        unsigned act = __ballot_sync(0xffffffffu, cmask != 0);
        if (!act) break;
        int leader = __ffs(act) - 1;
        int lbit   = __ffs(cmask) - 1;                       // valid on leader
        lbit = __shfl_sync(0xffffffffu, lbit, leader);
        int col = (lbit >> 2) * 128 + leader * 4 + (lbit & 3);
        if (lane == leader) cmask &= cmask - 1;

        const float* e = g_embT + (size_t)col * DIMD;
        *(float4*)&eb[wi][lane * 8]     = *(const float4*)(e + lane * 8);
        *(float4*)&eb[wi][lane * 8 + 4] = *(const float4*)(e + lane * 8 + 4);
        __syncwarp();
        if (lane == 0) {
            float s = 0.f;
            for (int k = 0; k < DIMD; k++)
                s = __fmaf_rn(xb[wi][k], eb[wi][k], s);       // EXACT ref chain
            float dv = __fadd_rn(__fsub_rn(xs, __fmul_rn(2.f, s)), g_esq[col]);
            ull key = ((ull)__float_as_uint(dv) << 32) | (unsigned)col;
            if (key < best) best = key;
        }
        __syncwarp();
    }
    best = __shfl_sync(0xffffffffu, best, 0);
    const unsigned ind = (unsigned)(best & 0xffffffffull);

    // gather winner + ste + diff
    const float* q = g_embT + (size_t)ind * DIMD;
    float4 qa = *(const float4*)(q + lane * 8);
    float4 qb = *(const float4*)(q + lane * 8 + 4);
    float qv[8] = { qa.x,qa.y,qa.z,qa.w, qb.x,qb.y,qb.z,qb.w };

    float* s1 = out + (size_t)z * ESZ + (size_t)row * DIMD + lane * 8;
    float* s2 = s1 + 2 * ESZ;
    float sv[8]; float accd = 0.f;
#pragma unroll
    for (int i = 0; i < 8; i++) {
        float d = __fsub_rn(qv[i], xr[i]);
        sv[i]   = __fadd_rn(xr[i], d);
        accd    = fmaf(d, d, accd);
    }
    *(float4*)(s1)     = make_float4(sv[0], sv[1], sv[2], sv[3]);
    *(float4*)(s1 + 4) = make_float4(sv[4], sv[5], sv[6], sv[7]);
    *(float4*)(s2)     = make_float4(sv[0], sv[1], sv[2], sv[3]);
    *(float4*)(s2 + 4) = make_float4(sv[4], sv[5], sv[6], sv[7]);

#pragma unroll
    for (int o = 16; o > 0; o >>= 1)
        accd += __shfl_xor_sync(0xffffffffu, accd, o);
    if (lane == 0) {
        atomicAdd(&g_diff[z], (double)accd);
        out[OFF_IND + (size_t)z * NROWS + row]            = (float)ind;
        out[OFF_IND + 65536ull + (size_t)z * NROWS + row] = (float)ind;
    }
}

// --------------------------------------------------------------- finalize
__global__ void k_final(float* __restrict__ out) {
    int t = threadIdx.x;
    if (t < 4) out[OFF_DIFF + t] = (float)(g_diff[t & 1] / 8388608.0);
}

extern "C" void kernel_launch(void* const* d_in, const int* in_sizes, int n_in,
                              void* d_out, int out_size)
{
    const float* hr = (const float*)d_in[0];
    const float* lr = (const float*)d_in[1];
    const float* em = (const float*)d_in[2];
    float* out = (float*)d_out;

    k_init<<<1, 32>>>();
    k_prep_rows<<<2048, 256>>>(hr, lr);
    k_prep_embed<<<128, 256>>>(em);
    dim3 g(KC / 128, NROWS / 128, 2);          // 8 x 256 x 2
    k_gemm<<<g, 256>>>(hr, lr, em, out);
    k_post<<<8192, 256>>>(hr, lr, out);
    k_final<<<1, 32>>>(out);
}

// round 12
// speedup vs baseline: 2.0963x; 1.4060x over previous
#include <cuda_runtime.h>
#include <cuda_bf16.h>
#include <cstdint>

typedef unsigned long long ull;

#define NROWS   32768      // rows per input tensor (8*64*64)
#define DIMD    256        // feature dim
#define KC      1024       // codebook size

// output layout (float32, tuple-concat order) — verified by passing R6/R10
#define ESZ      8388608ull    // one ste block (NROWS*DIMD)
#define DSZ      33554432ull   // one dist block (NROWS*KC)
#define OFF_DIFF 33554432ull   // after 4 ste blocks
#define OFF_IND  33554436ull   // after 4 diff scalars
#define OFF_DIST 33685508ull   // after 4 ind blocks (4*32768)

#define EPS_WIN  0.02f         // candidate window (>20x bf16 dist noise)

// scratch (static device globals — no allocations)
__device__ __align__(16) float         g_xsq[2 * NROWS];
__device__ __align__(16) float         g_esq[KC];
__device__ __align__(16) float         g_embT[KC * DIMD];
__device__ __align__(16) __nv_bfloat16 g_abf[2ull * NROWS * DIMD];   // [row][k] bf16
__device__ __align__(16) __nv_bfloat16 g_ebf[KC * DIMD];             // [col][k] bf16
__device__ double g_diff[2];

__device__ __forceinline__ uint32_t bf2(float x, float y) {
    __nv_bfloat162 h = __floats2bfloat162_rn(x, y);   // low = x, high = y
    return *(uint32_t*)&h;
}
__device__ __forceinline__ void cp_async16(uint32_t saddr, const void* gptr) {
    asm volatile("cp.async.ca.shared.global [%0], [%1], 16;" :: "r"(saddr), "l"(gptr));
}
__device__ __forceinline__ void cp_commit() { asm volatile("cp.async.commit_group;"); }
__device__ __forceinline__ void cp_wait0()  { asm volatile("cp.async.wait_group 0;"); }
__device__ __forceinline__ void ldsm4(uint32_t& r0, uint32_t& r1, uint32_t& r2, uint32_t& r3,
                                      uint32_t addr) {
    asm volatile("ldmatrix.sync.aligned.m8n8.x4.shared.b16 {%0,%1,%2,%3}, [%4];"
                 : "=r"(r0), "=r"(r1), "=r"(r2), "=r"(r3) : "r"(addr));
}

// ---------------------------------------------------------------- init
__global__ void k_init() {
    if (threadIdx.x < 2) g_diff[threadIdx.x] = 0.0;
}

// ------------------------------------------------- per-row ||x||^2 (bitwise path)
__global__ void k_prep_rows(const float* __restrict__ hr, const float* __restrict__ lr) {
    int w    = blockIdx.x * (blockDim.x >> 5) + (threadIdx.x >> 5);   // 16384 warps
    int lane = threadIdx.x & 31;
#pragma unroll
    for (int i = 0; i < 4; i++) {
        int row = w + i * 16384;                                      // 0..65535
        const float* x = (row >= NROWS) ? (lr + (size_t)(row - NROWS) * DIMD)
                                        : (hr + (size_t)row * DIMD);
        float s = 0.f;
#pragma unroll
        for (int j = 0; j < 8; j++) {
            float v = x[lane + (j << 5)];
            s = __fadd_rn(s, __fmul_rn(v, v));
        }
#pragma unroll
        for (int o = 16; o > 0; o >>= 1)
            s = __fadd_rn(s, __shfl_down_sync(0xffffffffu, s, o));
        if (lane == 0) g_xsq[row] = s;
    }
}

// -------------------------------- inputs -> bf16 [row][k] (GEMM-ready)
__global__ void k_prep_bf16(const float* __restrict__ hr, const float* __restrict__ lr) {
    size_t i = ((size_t)blockIdx.x * blockDim.x + threadIdx.x) * 8;   // 16,777,216 elems
    const float* src = (i < (size_t)NROWS * DIMD) ? hr + i
                                                  : lr + (i - (size_t)NROWS * DIMD);
    float4 a = *(const float4*)(src);
    float4 b = *(const float4*)(src + 4);
    uint4 u = { bf2(a.x, a.y), bf2(a.z, a.w), bf2(b.x, b.y), bf2(b.z, b.w) };
    *(uint4*)&g_abf[i] = u;
}

// ----------------- per-code ||e||^2 + fp32 embT + bf16 [col][k] codebook
__global__ void k_prep_embed(const float* __restrict__ embed) {
    int warp = blockIdx.x * (blockDim.x >> 5) + (threadIdx.x >> 5);   // 1024 warps
    int lane = threadIdx.x & 31;
    int c    = warp;
    float s = 0.f;
#pragma unroll
    for (int i = 0; i < 8; i++) {
        int d = lane + (i << 5);
        float v = embed[(size_t)d * KC + c];
        g_embT[(size_t)c * DIMD + d] = v;
        g_ebf [(size_t)c * DIMD + d] = __float2bfloat16_rn(v);
        s = __fadd_rn(s, __fmul_rn(v, v));
    }
#pragma unroll
    for (int o = 16; o > 0; o >>= 1)
        s = __fadd_rn(s, __shfl_down_sync(0xffffffffu, s, o));
    if (lane == 0) g_esq[c] = s;
}

// ------------------------------------------------ bf16 HMMA GEMM -> dist~
// CTA 128x128, BK=32, 8 warps (warp tile 32x64), cp.async staging from the
// pre-converted bf16 operands, ldmatrix.x4 fragment loads.
#define APITCH 40   // bf16 elems per smem row (80B: all 32 banks distinct per 8-row phase)

__global__ __launch_bounds__(256, 2) void k_gemm(float* __restrict__ out)
{
    __shared__ __nv_bfloat16 As[2][128][APITCH];   // [row][k]
    __shared__ __nv_bfloat16 Bs[2][128][APITCH];   // [col][k]
    __shared__ float sxs[128], sesq[128];

    const int z       = blockIdx.z;
    const int rowBase = blockIdx.y << 7;
    const int colBase = blockIdx.x << 7;
    const int tid     = threadIdx.x;
    const int lane    = tid & 31, wid = tid >> 5;
    const int wm      = wid >> 1, wn = wid & 1;       // warp grid 4x2
    const int gid     = lane >> 2, t4 = lane & 3;

    if (tid < 128) {
        sxs[tid]  = g_xsq[(size_t)z * NROWS + rowBase + tid];
        sesq[tid] = g_esq[colBase + tid];
    }

    // staging: 4 chunks of 16B per thread per stage (2 A rows, 2 B rows)
    const int sr = tid >> 2;            // 0..63
    const int sc = (tid & 3) << 3;      // k-elem offset 0,8,16,24
    const __nv_bfloat16* Ag = g_abf + (size_t)(z * NROWS + rowBase) * DIMD;
    const __nv_bfloat16* Bg = g_ebf + (size_t)colBase * DIMD;

    float acc[2][8][4];
#pragma unroll
    for (int m = 0; m < 2; m++)
#pragma unroll
        for (int n = 0; n < 8; n++)
#pragma unroll
            for (int c = 0; c < 4; c++) acc[m][n][c] = 0.f;

    const uint32_t sA = (uint32_t)__cvta_generic_to_shared(&As[0][0][0]);
    const uint32_t sB = (uint32_t)__cvta_generic_to_shared(&Bs[0][0][0]);
    const uint32_t stageBytes = 128 * APITCH * 2;   // one buffer

    auto issue_stage = [&](int nb, int kb) {
        const size_t go = (size_t)kb * 32 + sc;
        cp_async16(sA + nb * stageBytes + (sr * APITCH + sc) * 2,
                   Ag + (size_t)sr * DIMD + go);
        cp_async16(sA + nb * stageBytes + ((sr + 64) * APITCH + sc) * 2,
                   Ag + (size_t)(sr + 64) * DIMD + go);
        cp_async16(sB + nb * stageBytes + (sr * APITCH + sc) * 2,
                   Bg + (size_t)sr * DIMD + go);
        cp_async16(sB + nb * stageBytes + ((sr + 64) * APITCH + sc) * 2,
                   Bg + (size_t)(sr + 64) * DIMD + go);
        cp_commit();
    };

    issue_stage(0, 0);

    for (int kb = 0; kb < 8; kb++) {
        const int buf = kb & 1;
        cp_wait0();
        __syncthreads();
        if (kb < 7) issue_stage(buf ^ 1, kb + 1);   // overlaps compute below

#pragma unroll
        for (int ks = 0; ks < 2; ks++) {
            const int kk = ks * 16;
            // B fragments: 4 ldmatrix.x4 (two n-tiles each)
            uint32_t bfr[8][2];
#pragma unroll
            for (int p = 0; p < 4; p++) {
                const int n0 = wn * 64 + p * 16;
                const int brow = n0 + (lane & 7) + ((lane >> 4) << 3);
                const int bcol = kk + (((lane >> 3) & 1) << 3);
                uint32_t addr = sB + buf * stageBytes + (brow * APITCH + bcol) * 2;
                ldsm4(bfr[p*2][0], bfr[p*2][1], bfr[p*2+1][0], bfr[p*2+1][1], addr);
            }
            // A fragments + mma
#pragma unroll
            for (int m = 0; m < 2; m++) {
                const int r0 = wm * 32 + m * 16;
                const int arow = r0 + (lane & 7) + (((lane >> 3) & 1) << 3);
                const int acol = kk + ((lane >> 4) << 3);
                uint32_t a0, a1, a2, a3;
                ldsm4(a0, a1, a2, a3,
                      sA + buf * stageBytes + (arow * APITCH + acol) * 2);
#pragma unroll
                for (int n = 0; n < 8; n++) {
                    asm volatile(
                        "mma.sync.aligned.m16n8k16.row.col.f32.bf16.bf16.f32 "
                        "{%0,%1,%2,%3}, {%4,%5,%6,%7}, {%8,%9}, {%0,%1,%2,%3};"
                        : "+f"(acc[m][n][0]), "+f"(acc[m][n][1]),
                          "+f"(acc[m][n][2]), "+f"(acc[m][n][3])
                        : "r"(a0), "r"(a1), "r"(a2), "r"(a3),
                          "r"(bfr[n][0]), "r"(bfr[n][1]));
                }
            }
        }
        __syncthreads();
    }

    // epilogue: dist~ = xs - 2S + esq ; write both duplicate blocks
#pragma unroll
    for (int m = 0; m < 2; m++) {
#pragma unroll
        for (int half = 0; half < 2; half++) {
            const int r    = wm * 32 + m * 16 + gid + half * 8;
            const int grow = rowBase + r;
            const float xs = sxs[r];
            size_t rbase = OFF_DIST + (size_t)z * DSZ + (size_t)grow * KC + colBase;
#pragma unroll
            for (int n = 0; n < 8; n++) {
                const int lc = wn * 64 + n * 8 + t4 * 2;
                float s0 = acc[m][n][half * 2 + 0];
                float s1 = acc[m][n][half * 2 + 1];
                float2 dv = make_float2(fmaf(-2.f, s0, xs) + sesq[lc],
                                        fmaf(-2.f, s1, xs) + sesq[lc + 1]);
                *(float2*)(out + rbase + lc)           = dv;
                *(float2*)(out + rbase + lc + 2 * DSZ) = dv;
            }
        }
    }
}

// ---------------- post: exact argmin recheck + ste + ind + diff (warp/row)
__global__ __launch_bounds__(256) void k_post(
    const float* __restrict__ hr, const float* __restrict__ lr,
    float* __restrict__ out)
{
    __shared__ float xb[8][DIMD];
    __shared__ float eb[8][DIMD];

    const int wi   = threadIdx.x >> 5;
    const int lane = threadIdx.x & 31;
    const int w    = blockIdx.x * 8 + wi;          // 0..65535
    const int z    = w >> 15;
    const int row  = w & 32767;

    const float* x = (z ? lr : hr) + (size_t)row * DIMD;
    float xr[8];
    {
        float4 a = *(const float4*)(x + lane * 8);
        float4 b = *(const float4*)(x + lane * 8 + 4);
        xr[0]=a.x; xr[1]=a.y; xr[2]=a.z; xr[3]=a.w;
        xr[4]=b.x; xr[5]=b.y; xr[6]=b.z; xr[7]=b.w;
        *(float4*)&xb[wi][lane * 8]     = a;
        *(float4*)&xb[wi][lane * 8 + 4] = b;
    }
    const float xs = g_xsq[(size_t)z * NROWS + row];
    __syncwarp();

    // scan this row's approximate dists, find min + candidates
    const float* drow = out + OFF_DIST + (size_t)z * DSZ + (size_t)row * KC;
    float4 v[8];
    float mn = 3.4e38f;
#pragma unroll
    for (int j = 0; j < 8; j++) {
        v[j] = *(const float4*)(drow + j * 128 + lane * 4);
        mn = fminf(mn, fminf(fminf(v[j].x, v[j].y), fminf(v[j].z, v[j].w)));
    }
#pragma unroll
    for (int o = 16; o > 0; o >>= 1)
        mn = fminf(mn, __shfl_xor_sync(0xffffffffu, mn, o));
    const float thr = mn + EPS_WIN;

    unsigned cmask = 0;
#pragma unroll
    for (int j = 0; j < 8; j++) {
        if (v[j].x <= thr) cmask |= 1u << (j * 4 + 0);
        if (v[j].y <= thr) cmask |= 1u << (j * 4 + 1);
        if (v[j].z <= thr) cmask |= 1u << (j * 4 + 2);
        if (v[j].w <= thr) cmask |= 1u << (j * 4 + 3);
    }

    ull best = ~0ull;
    while (true) {
        unsigned act = __ballot_sync(0xffffffffu, cmask != 0);
        if (!act) break;
        int leader = __ffs(act) - 1;
        int lbit   = __ffs(cmask) - 1;                       // valid on leader
        lbit = __shfl_sync(0xffffffffu, lbit, leader);
        int col = (lbit >> 2) * 128 + leader * 4 + (lbit & 3);
        if (lane == leader) cmask &= cmask - 1;

        const float* e = g_embT + (size_t)col * DIMD;
        *(float4*)&eb[wi][lane * 8]     = *(const float4*)(e + lane * 8);
        *(float4*)&eb[wi][lane * 8 + 4] = *(const float4*)(e + lane * 8 + 4);
        __syncwarp();
        if (lane == 0) {
            float s = 0.f;
            for (int k = 0; k < DIMD; k++)
                s = __fmaf_rn(xb[wi][k], eb[wi][k], s);       // EXACT ref chain
            float dv = __fadd_rn(__fsub_rn(xs, __fmul_rn(2.f, s)), g_esq[col]);
            ull key = ((ull)__float_as_uint(dv) << 32) | (unsigned)col;
            if (key < best) best = key;
        }
        __syncwarp();
    }
    best = __shfl_sync(0xffffffffu, best, 0);
    const unsigned ind = (unsigned)(best & 0xffffffffull);

    // gather winner + ste + diff
    const float* q = g_embT + (size_t)ind * DIMD;
    float4 qa = *(const float4*)(q + lane * 8);
    float4 qb = *(const float4*)(q + lane * 8 + 4);
    float qv[8] = { qa.x,qa.y,qa.z,qa.w, qb.x,qb.y,qb.z,qb.w };

    float* s1 = out + (size_t)z * ESZ + (size_t)row * DIMD + lane * 8;
    float* s2 = s1 + 2 * ESZ;
    float sv[8]; float accd = 0.f;
#pragma unroll
    for (int i = 0; i < 8; i++) {
        float d = __fsub_rn(qv[i], xr[i]);
        sv[i]   = __fadd_rn(xr[i], d);
        accd    = fmaf(d, d, accd);
    }
    *(float4*)(s1)     = make_float4(sv[0], sv[1], sv[2], sv[3]);
    *(float4*)(s1 + 4) = make_float4(sv[4], sv[5], sv[6], sv[7]);
    *(float4*)(s2)     = make_float4(sv[0], sv[1], sv[2], sv[3]);
    *(float4*)(s2 + 4) = make_float4(sv[4], sv[5], sv[6], sv[7]);

#pragma unroll
    for (int o = 16; o > 0; o >>= 1)
        accd += __shfl_xor_sync(0xffffffffu, accd, o);
    if (lane == 0) {
        atomicAdd(&g_diff[z], (double)accd);
        out[OFF_IND + (size_t)z * NROWS + row]            = (float)ind;
        out[OFF_IND + 65536ull + (size_t)z * NROWS + row] = (float)ind;
    }
}

// --------------------------------------------------------------- finalize
__global__ void k_final(float* __restrict__ out) {
    int t = threadIdx.x;
    if (t < 4) out[OFF_DIFF + t] = (float)(g_diff[t & 1] / 8388608.0);
}

extern "C" void kernel_launch(void* const* d_in, const int* in_sizes, int n_in,
                              void* d_out, int out_size)
{
    const float* hr = (const float*)d_in[0];
    const float* lr = (const float*)d_in[1];
    const float* em = (const float*)d_in[2];
    float* out = (float*)d_out;

    k_init<<<1, 32>>>();
    k_prep_rows<<<2048, 256>>>(hr, lr);
    k_prep_bf16<<<8192, 256>>>(hr, lr);
    k_prep_embed<<<128, 256>>>(em);
    dim3 g(KC / 128, NROWS / 128, 2);          // 8 x 256 x 2
    k_gemm<<<g, 256>>>(out);
    k_post<<<8192, 256>>>(hr, lr, out);
    k_final<<<1, 32>>>(out);
}